// round 10
// baseline (speedup 1.0000x reference)
#include <cuda_runtime.h>
#include <cuda_fp16.h>
#include <cstdint>

// ---------------- problem constants ----------------
#define M_TOTAL 8192
#define K_DIM   4096
#define N_DIM   4096
#define LRANK   16

#define TM 128
#define TN 256
#define KC 64                     // fp16 elems per k-chunk (128B rows, SW128)
#define NCHUNK (K_DIM / KC)       // 64
#define MT (M_TOTAL / TM)         // 64
#define NT (N_DIM / TN)           // 16

#define A_BLK 16384               // 128x64 fp16
#define W_BLK 32768               // 256x64 fp16
#define STAGE_BYTES 49152         // A_BLK + W_BLK
#define NSTAGE 3
#define SMEM_TOTAL (NSTAGE * STAGE_BYTES)   // 147456 -> 1 CTA/SM

// pre-converted, pre-swizzled operands (device globals = sanctioned scratch)
__device__ __align__(1024) unsigned char g_x[(size_t)MT * NCHUNK * A_BLK]; // 64MB
__device__ __align__(1024) unsigned char g_w[(size_t)NT * NCHUNK * W_BLK]; // 32MB

static __device__ __forceinline__ uint32_t smem_u32(const void* p) {
    uint32_t a;
    asm("{ .reg .u64 t; cvta.to.shared.u64 t, %1; cvt.u32.u64 %0, t; }" : "=r"(a) : "l"(p));
    return a;
}

static __device__ __forceinline__ void cp16(uint32_t dst, const void* src) {
    asm volatile("cp.async.cg.shared.global [%0], [%1], 16;" :: "r"(dst), "l"(src) : "memory");
}

#define LDSM_X4(r0, r1, r2, r3, addr)                                          \
    asm volatile("ldmatrix.sync.aligned.m8n8.x4.shared.b16 {%0,%1,%2,%3}, [%4];" \
        : "=r"(r0), "=r"(r1), "=r"(r2), "=r"(r3) : "r"(addr))

#define MMA16816(d, a0, a1, a2, a3, b0, b1)                                    \
    asm volatile("mma.sync.aligned.m16n8k16.row.col.f32.f16.f16.f32 "          \
        "{%0,%1,%2,%3}, {%4,%5,%6,%7}, {%8,%9}, {%0,%1,%2,%3};"                \
        : "+f"((d)[0]), "+f"((d)[1]), "+f"((d)[2]), "+f"((d)[3])               \
        : "r"(a0), "r"(a1), "r"(a2), "r"(a3), "r"(b0), "r"(b1))

// ===========================================================================
// conv_x: x fp32 -> fp16, SW128-swizzled 128x64 blocks
// ===========================================================================
__global__ __launch_bounds__(256)
void conv_x_kernel(const float* __restrict__ x)
{
    const int kc = blockIdx.x, mt = blockIdx.y;
    const int k0 = kc * KC, m0 = mt * TM;
    unsigned char* blk = g_x + ((size_t)(mt * NCHUNK + kc) * A_BLK);
    const int t = threadIdx.x;
    #pragma unroll
    for (int i = 0; i < (TM * KC) / 256; i++) {
        int e = t + 256 * i;
        int r = e >> 6, c = e & 63;
        float v = x[(size_t)(m0 + r) * K_DIM + k0 + c];
        uint32_t off = (uint32_t)r * 128 + (uint32_t)c * 2;
        uint32_t sw = off ^ ((off >> 3) & 0x70);
        *(__half*)(blk + sw) = __float2half_rn(v);
    }
}

// ===========================================================================
// conv_w: W' = W + B@A -> fp16, SW128-swizzled 256x64 blocks
// grid (NCHUNK, 64): each block does 64 n-rows x 64 k-cols
// n_tile = by>>2 (256-row tiles), row_base = (by&3)*64
// ===========================================================================
__global__ __launch_bounds__(256)
void conv_w_kernel(const float* __restrict__ W, const float* __restrict__ Amat,
                   const float* __restrict__ Bmat)
{
    __shared__ float As[16][64];
    __shared__ float Bs[64][16];
    const int kc = blockIdx.x, by = blockIdx.y;
    const int k0 = kc * KC, n0 = by * 64;
    const int t = threadIdx.x;

    {   // A slab 16x64
        int r = t / 16, c4 = (t % 16) * 4;
        float4 v = *(const float4*)&Amat[(size_t)r * K_DIM + k0 + c4];
        As[r][c4+0] = v.x; As[r][c4+1] = v.y; As[r][c4+2] = v.z; As[r][c4+3] = v.w;
    }
    {   // B slab 64x16
        int nl = t / 4, r4 = (t % 4) * 4;
        float4 v = *(const float4*)&Bmat[(size_t)(n0 + nl) * LRANK + r4];
        Bs[nl][r4+0] = v.x; Bs[nl][r4+1] = v.y; Bs[nl][r4+2] = v.z; Bs[nl][r4+3] = v.w;
    }
    __syncthreads();

    const int n_tile = by >> 2;            // 256-row tiles
    const int row_base = (by & 3) * 64;
    unsigned char* blk = g_w + ((size_t)(n_tile * NCHUNK + kc) * W_BLK);

    #pragma unroll
    for (int i = 0; i < 16; i++) {
        int e = t + 256 * i;
        int rl = e >> 6, c = e & 63;
        float acc = W[(size_t)(n0 + rl) * K_DIM + k0 + c];
        #pragma unroll
        for (int r = 0; r < 16; r++) acc += Bs[rl][r] * As[r][c];
        uint32_t off = (uint32_t)(row_base + rl) * 128 + (uint32_t)c * 2;
        uint32_t sw = off ^ ((off >> 3) & 0x70);
        *(__half*)(blk + sw) = __float2half_rn(acc);
    }
}

// ===========================================================================
// GEMM: out = x @ W'^T + bias  via fp16 HMMA (mma.sync)
// CTA 128x256, 16 warps (4x4), warp tile 32x64, 3-stage, 1 barrier/chunk
// ===========================================================================
__global__ __launch_bounds__(512, 1)
void gemm_mma_kernel(const float* __restrict__ bias, float* __restrict__ out)
{
    extern __shared__ __align__(1024) unsigned char smem[];
    const uint32_t sbase = smem_u32(smem);
    const int tid  = threadIdx.x;
    const int lane = tid & 31;
    const int wid  = tid >> 5;
    const int wm   = wid & 3;          // 4 m-groups of 32
    const int wn   = wid >> 2;         // 4 n-groups of 64
    const int nt = blockIdx.x, mt = blockIdx.y;
    const int m0 = mt * TM, n0 = nt * TN;

    const unsigned char* ga = g_x + (size_t)(mt * NCHUNK) * A_BLK;
    const unsigned char* gb = g_w + (size_t)(nt * NCHUNK) * W_BLK;

    // ---- per-thread ldmatrix addressing (SW128) ----
    const int aRow = wm * 32 + ((lane >> 3) & 1) * 8 + (lane & 7);
    const uint32_t aKsel = (lane >> 4) * 16;            // +16B for k+8 halves
    const int bRow = wn * 64 + ((lane >> 4) & 1) * 8 + (lane & 7);
    const uint32_t bKsel = ((lane >> 3) & 1) * 16;
    const uint32_t X = (uint32_t)(lane & 7) << 4;       // swizzle XOR (row&7)<<4

    float acc[2][8][4];
    #pragma unroll
    for (int i = 0; i < 2; i++)
        #pragma unroll
        for (int j = 0; j < 8; j++)
            #pragma unroll
            for (int q = 0; q < 4; q++) acc[i][j][q] = 0.f;

    // ---- async copy of one chunk into stage s (512 threads) ----
    auto issue = [&](int c, int s) {
        const unsigned char* srcA = ga + (size_t)c * A_BLK;
        const unsigned char* srcB = gb + (size_t)c * W_BLK;
        uint32_t st = sbase + s * STAGE_BYTES;
        #pragma unroll
        for (int i = 0; i < 2; i++) {                      // A: 16KB
            uint32_t off = (uint32_t)tid * 16 + i * 8192;
            cp16(st + off, srcA + off);
        }
        #pragma unroll
        for (int i = 0; i < 4; i++) {                      // B: 32KB
            uint32_t off = (uint32_t)tid * 16 + i * 8192;
            cp16(st + A_BLK + off, srcB + off);
        }
        asm volatile("cp.async.commit_group;" ::: "memory");
    };

    issue(0, 0);
    issue(1, 1);

    int s = 0, spre = 2;
    for (int c = 0; c < NCHUNK; c++) {
        asm volatile("cp.async.wait_group 1;" ::: "memory");
        __syncthreads();
        // stage spre = (c+2)%3 == (c-1)%3 was fully consumed before this barrier
        if (c + 2 < NCHUNK) issue(c + 2, spre);

        const uint32_t Ahi = sbase + s * STAGE_BYTES;
        const uint32_t Bhi = Ahi + A_BLK;

        #pragma unroll
        for (int ks = 0; ks < 4; ks++) {
            const uint32_t kb = (uint32_t)ks * 32;           // k0*2 bytes
            const uint32_t aoff = (kb + aKsel) ^ X;
            const uint32_t boff = (kb + bKsel) ^ X;

            uint32_t aH[2][4];
            #pragma unroll
            for (int m2 = 0; m2 < 2; m2++) {
                uint32_t rb = (uint32_t)(aRow + 16 * m2) * 128;
                LDSM_X4(aH[m2][0], aH[m2][1], aH[m2][2], aH[m2][3], Ahi + rb + aoff);
            }
            uint32_t bH[4][4];
            #pragma unroll
            for (int n4 = 0; n4 < 4; n4++) {
                uint32_t rb = (uint32_t)(bRow + 16 * n4) * 128;
                LDSM_X4(bH[n4][0], bH[n4][1], bH[n4][2], bH[n4][3], Bhi + rb + boff);
            }

            #pragma unroll
            for (int m2 = 0; m2 < 2; m2++) {
                #pragma unroll
                for (int nj = 0; nj < 8; nj++) {
                    const int g = nj >> 1, h = (nj & 1) * 2;
                    MMA16816(acc[m2][nj], aH[m2][0], aH[m2][1], aH[m2][2], aH[m2][3],
                             bH[g][h], bH[g][h + 1]);
                }
            }
        }

        s = (s == NSTAGE - 1) ? 0 : s + 1;
        spre = (spre == NSTAGE - 1) ? 0 : spre + 1;
    }

    // ---- epilogue: bias + store ----
    const int rrow = m0 + wm * 32 + (lane >> 2);
    const int ncol = n0 + wn * 64 + (lane & 3) * 2;

    float2 bb[8];
    #pragma unroll
    for (int nj = 0; nj < 8; nj++)
        bb[nj] = *(const float2*)&bias[ncol + nj * 8];

    #pragma unroll
    for (int m2 = 0; m2 < 2; m2++) {
        #pragma unroll
        for (int nj = 0; nj < 8; nj++) {
            const int n = ncol + nj * 8;
            size_t r0 = (size_t)(rrow + m2 * 16) * N_DIM + n;
            size_t r1 = r0 + 8 * N_DIM;
            float2 o0, o1;
            o0.x = acc[m2][nj][0] + bb[nj].x;
            o0.y = acc[m2][nj][1] + bb[nj].y;
            o1.x = acc[m2][nj][2] + bb[nj].x;
            o1.y = acc[m2][nj][3] + bb[nj].y;
            *(float2*)&out[r0] = o0;
            *(float2*)&out[r1] = o1;
        }
    }
}

// ===========================================================================
extern "C" void kernel_launch(void* const* d_in, const int* in_sizes, int n_in,
                              void* d_out, int out_size)
{
    (void)in_sizes; (void)n_in; (void)out_size;
    const float* x    = (const float*)d_in[0];
    const float* W    = (const float*)d_in[1];
    const float* bias = (const float*)d_in[2];
    const float* A    = (const float*)d_in[3];
    const float* Bm   = (const float*)d_in[4];
    float* out        = (float*)d_out;

    cudaFuncSetAttribute(gemm_mma_kernel,
                         cudaFuncAttributeMaxDynamicSharedMemorySize, SMEM_TOTAL);

    conv_x_kernel<<<dim3(NCHUNK, MT), 256>>>(x);
    conv_w_kernel<<<dim3(NCHUNK, 64), 256>>>(W, A, Bm);
    gemm_mma_kernel<<<dim3(NT, MT), 512, SMEM_TOTAL>>>(bias, out);
}

// round 11
// speedup vs baseline: 1.0419x; 1.0419x over previous
#include <cuda_runtime.h>
#include <cuda_fp16.h>
#include <cstdint>

// ---------------- problem constants ----------------
#define M_TOTAL 8192
#define K_DIM   4096
#define N_DIM   4096
#define LRANK   16

#define TM 128
#define TN 128
#define KC 64                     // fp16 elems per k-chunk (128B rows, SW128)
#define NCHUNK (K_DIM / KC)       // 64
#define MT (M_TOTAL / TM)         // 64
#define NT (N_DIM / TN)           // 32

#define A_BLK 16384               // 128x64 fp16
#define W_BLK 16384               // 128x64 fp16
#define STAGE_BYTES 32768         // A_BLK + W_BLK
#define NSTAGE 3
#define SMEM_TOTAL (NSTAGE * STAGE_BYTES)   // 98304 -> 2 CTAs/SM

// pre-converted, pre-swizzled operands (device globals = sanctioned scratch)
__device__ __align__(1024) unsigned char g_x[(size_t)MT * NCHUNK * A_BLK]; // 64MB
__device__ __align__(1024) unsigned char g_w[(size_t)NT * NCHUNK * W_BLK]; // 32MB

static __device__ __forceinline__ uint32_t smem_u32(const void* p) {
    uint32_t a;
    asm("{ .reg .u64 t; cvta.to.shared.u64 t, %1; cvt.u32.u64 %0, t; }" : "=r"(a) : "l"(p));
    return a;
}

static __device__ __forceinline__ void cp16(uint32_t dst, const void* src) {
    asm volatile("cp.async.cg.shared.global [%0], [%1], 16;" :: "r"(dst), "l"(src) : "memory");
}

#define LDSM_X4(r0, r1, r2, r3, addr)                                          \
    asm volatile("ldmatrix.sync.aligned.m8n8.x4.shared.b16 {%0,%1,%2,%3}, [%4];" \
        : "=r"(r0), "=r"(r1), "=r"(r2), "=r"(r3) : "r"(addr))

#define MMA16816(d, a0, a1, a2, a3, b0, b1)                                    \
    asm volatile("mma.sync.aligned.m16n8k16.row.col.f32.f16.f16.f32 "          \
        "{%0,%1,%2,%3}, {%4,%5,%6,%7}, {%8,%9}, {%0,%1,%2,%3};"                \
        : "+f"((d)[0]), "+f"((d)[1]), "+f"((d)[2]), "+f"((d)[3])               \
        : "r"(a0), "r"(a1), "r"(a2), "r"(a3), "r"(b0), "r"(b1))

// pack 8 floats -> 8 halves (uint4)
static __device__ __forceinline__ uint4 pack8(const float* v) {
    union { uint4 u; __half2 h[4]; } o;
    o.h[0] = __float22half2_rn(make_float2(v[0], v[1]));
    o.h[1] = __float22half2_rn(make_float2(v[2], v[3]));
    o.h[2] = __float22half2_rn(make_float2(v[4], v[5]));
    o.h[3] = __float22half2_rn(make_float2(v[6], v[7]));
    return o.u;
}

// ===========================================================================
// conv_x: x fp32 -> fp16, SW128-swizzled 128x64 blocks
// 8 contiguous k-elems per thread -> one 16B store (swizzle is 16B-granular)
// ===========================================================================
__global__ __launch_bounds__(256)
void conv_x_kernel(const float* __restrict__ x)
{
    const int kc = blockIdx.x, mt = blockIdx.y;
    const int k0 = kc * KC, m0 = mt * TM;
    unsigned char* blk = g_x + ((size_t)(mt * NCHUNK + kc) * A_BLK);
    const int t = threadIdx.x;
    #pragma unroll
    for (int i = 0; i < 4; i++) {                 // 1024 items of 8 elems
        int e = t + 256 * i;
        int r = e >> 3, c8 = (e & 7) * 8;
        const float* src = &x[(size_t)(m0 + r) * K_DIM + k0 + c8];
        float v[8];
        *(float4*)&v[0] = *(const float4*)(src);
        *(float4*)&v[4] = *(const float4*)(src + 4);
        uint32_t off = (uint32_t)r * 128 + (uint32_t)c8 * 2;
        uint32_t sw = off ^ ((off >> 3) & 0x70);
        *(uint4*)(blk + sw) = pack8(v);
    }
}

// ===========================================================================
// conv_w: W' = W + B@A -> fp16, SW128-swizzled 128x64 blocks
// grid (NCHUNK, 64): each block does 64 n-rows x 64 k-cols
// ===========================================================================
__global__ __launch_bounds__(256)
void conv_w_kernel(const float* __restrict__ W, const float* __restrict__ Amat,
                   const float* __restrict__ Bmat)
{
    __shared__ float As[16][64];
    __shared__ float Bs[64][16];
    const int kc = blockIdx.x, by = blockIdx.y;
    const int k0 = kc * KC, n0 = by * 64;
    const int t = threadIdx.x;

    {   // A slab 16x64
        int r = t / 16, c4 = (t % 16) * 4;
        float4 v = *(const float4*)&Amat[(size_t)r * K_DIM + k0 + c4];
        As[r][c4+0] = v.x; As[r][c4+1] = v.y; As[r][c4+2] = v.z; As[r][c4+3] = v.w;
    }
    {   // B slab 64x16
        int nl = t / 4, r4 = (t % 4) * 4;
        float4 v = *(const float4*)&Bmat[(size_t)(n0 + nl) * LRANK + r4];
        Bs[nl][r4+0] = v.x; Bs[nl][r4+1] = v.y; Bs[nl][r4+2] = v.z; Bs[nl][r4+3] = v.w;
    }
    __syncthreads();

    const int n_tile = by >> 1;            // 128-row tiles
    const int row_base = (by & 1) * 64;
    unsigned char* blk = g_w + ((size_t)(n_tile * NCHUNK + kc) * W_BLK);

    #pragma unroll
    for (int i = 0; i < 2; i++) {                 // 512 items of 8 elems
        int e = t + 256 * i;
        int rl = e >> 3, c8 = (e & 7) * 8;
        const float* src = &W[(size_t)(n0 + rl) * K_DIM + k0 + c8];
        float v[8];
        *(float4*)&v[0] = *(const float4*)(src);
        *(float4*)&v[4] = *(const float4*)(src + 4);
        #pragma unroll
        for (int r = 0; r < 16; r++) {
            float b = Bs[rl][r];
            #pragma unroll
            for (int j = 0; j < 8; j++) v[j] += b * As[r][c8 + j];
        }
        uint32_t off = (uint32_t)(row_base + rl) * 128 + (uint32_t)c8 * 2;
        uint32_t sw = off ^ ((off >> 3) & 0x70);
        *(uint4*)(blk + sw) = pack8(v);
    }
}

// ===========================================================================
// GEMM: out = x @ W'^T + bias  via fp16 HMMA (mma.sync)
// CTA 128x128, 8 warps (4x2), warp tile 32x64, 3-stage, 1 barrier/chunk,
// 2 CTAs/SM for cross-CTA prologue/epilogue overlap
// ===========================================================================
__global__ __launch_bounds__(256, 2)
void gemm_mma_kernel(const float* __restrict__ bias, float* __restrict__ out)
{
    extern __shared__ __align__(1024) unsigned char smem[];
    const uint32_t sbase = smem_u32(smem);
    const int tid  = threadIdx.x;
    const int lane = tid & 31;
    const int wid  = tid >> 5;
    const int wm   = wid & 3;          // 4 m-groups of 32
    const int wn   = wid >> 2;         // 2 n-groups of 64
    const int nt = blockIdx.x, mt = blockIdx.y;
    const int m0 = mt * TM, n0 = nt * TN;

    const unsigned char* ga = g_x + (size_t)(mt * NCHUNK) * A_BLK;
    const unsigned char* gb = g_w + (size_t)(nt * NCHUNK) * W_BLK;

    // ---- per-thread ldmatrix addressing (SW128) ----
    const int aRow = wm * 32 + ((lane >> 3) & 1) * 8 + (lane & 7);
    const uint32_t aKsel = (lane >> 4) * 16;            // +16B for k+8 halves
    const int bRow = wn * 64 + ((lane >> 4) & 1) * 8 + (lane & 7);
    const uint32_t bKsel = ((lane >> 3) & 1) * 16;
    const uint32_t X = (uint32_t)(lane & 7) << 4;       // swizzle XOR (row&7)<<4

    float acc[2][8][4];
    #pragma unroll
    for (int i = 0; i < 2; i++)
        #pragma unroll
        for (int j = 0; j < 8; j++)
            #pragma unroll
            for (int q = 0; q < 4; q++) acc[i][j][q] = 0.f;

    // ---- async copy of one chunk into stage s (256 threads) ----
    auto issue = [&](int c, int s) {
        const unsigned char* srcA = ga + (size_t)c * A_BLK;
        const unsigned char* srcB = gb + (size_t)c * W_BLK;
        uint32_t st = sbase + s * STAGE_BYTES;
        #pragma unroll
        for (int i = 0; i < 4; i++) {                      // A: 16KB
            uint32_t off = (uint32_t)tid * 16 + i * 4096;
            cp16(st + off, srcA + off);
        }
        #pragma unroll
        for (int i = 0; i < 4; i++) {                      // B: 16KB
            uint32_t off = (uint32_t)tid * 16 + i * 4096;
            cp16(st + A_BLK + off, srcB + off);
        }
        asm volatile("cp.async.commit_group;" ::: "memory");
    };

    issue(0, 0);
    issue(1, 1);

    int s = 0, spre = 2;
    for (int c = 0; c < NCHUNK; c++) {
        asm volatile("cp.async.wait_group 1;" ::: "memory");
        __syncthreads();
        // stage spre = (c+2)%3 == (c-1)%3 was fully consumed before this barrier
        if (c + 2 < NCHUNK) issue(c + 2, spre);

        const uint32_t Ahi = sbase + s * STAGE_BYTES;
        const uint32_t Bhi = Ahi + A_BLK;

        #pragma unroll
        for (int ks = 0; ks < 4; ks++) {
            const uint32_t kb = (uint32_t)ks * 32;           // k0*2 bytes
            const uint32_t aoff = (kb + aKsel) ^ X;
            const uint32_t boff = (kb + bKsel) ^ X;

            uint32_t aH[2][4];
            #pragma unroll
            for (int m2 = 0; m2 < 2; m2++) {
                uint32_t rb = (uint32_t)(aRow + 16 * m2) * 128;
                LDSM_X4(aH[m2][0], aH[m2][1], aH[m2][2], aH[m2][3], Ahi + rb + aoff);
            }
            uint32_t bH[4][4];
            #pragma unroll
            for (int n4 = 0; n4 < 4; n4++) {
                uint32_t rb = (uint32_t)(bRow + 16 * n4) * 128;
                LDSM_X4(bH[n4][0], bH[n4][1], bH[n4][2], bH[n4][3], Bhi + rb + boff);
            }

            #pragma unroll
            for (int m2 = 0; m2 < 2; m2++) {
                #pragma unroll
                for (int nj = 0; nj < 8; nj++) {
                    const int g = nj >> 1, h = (nj & 1) * 2;
                    MMA16816(acc[m2][nj], aH[m2][0], aH[m2][1], aH[m2][2], aH[m2][3],
                             bH[g][h], bH[g][h + 1]);
                }
            }
        }

        s = (s == NSTAGE - 1) ? 0 : s + 1;
        spre = (spre == NSTAGE - 1) ? 0 : spre + 1;
    }

    // ---- epilogue: bias + store ----
    const int rrow = m0 + wm * 32 + (lane >> 2);
    const int ncol = n0 + wn * 64 + (lane & 3) * 2;

    float2 bb[8];
    #pragma unroll
    for (int nj = 0; nj < 8; nj++)
        bb[nj] = *(const float2*)&bias[ncol + nj * 8];

    #pragma unroll
    for (int m2 = 0; m2 < 2; m2++) {
        #pragma unroll
        for (int nj = 0; nj < 8; nj++) {
            const int n = ncol + nj * 8;
            size_t r0 = (size_t)(rrow + m2 * 16) * N_DIM + n;
            size_t r1 = r0 + 8 * N_DIM;
            float2 o0, o1;
            o0.x = acc[m2][nj][0] + bb[nj].x;
            o0.y = acc[m2][nj][1] + bb[nj].y;
            o1.x = acc[m2][nj][2] + bb[nj].x;
            o1.y = acc[m2][nj][3] + bb[nj].y;
            *(float2*)&out[r0] = o0;
            *(float2*)&out[r1] = o1;
        }
    }
}

// ===========================================================================
extern "C" void kernel_launch(void* const* d_in, const int* in_sizes, int n_in,
                              void* d_out, int out_size)
{
    (void)in_sizes; (void)n_in; (void)out_size;
    const float* x    = (const float*)d_in[0];
    const float* W    = (const float*)d_in[1];
    const float* bias = (const float*)d_in[2];
    const float* A    = (const float*)d_in[3];
    const float* Bm   = (const float*)d_in[4];
    float* out        = (float*)d_out;

    cudaFuncSetAttribute(gemm_mma_kernel,
                         cudaFuncAttributeMaxDynamicSharedMemorySize, SMEM_TOTAL);

    conv_x_kernel<<<dim3(NCHUNK, MT), 256>>>(x);
    conv_w_kernel<<<dim3(NCHUNK, 64), 256>>>(W, A, Bm);
    gemm_mma_kernel<<<dim3(NT, MT), 256, SMEM_TOTAL>>>(bias, out);
}

// round 12
// speedup vs baseline: 1.0480x; 1.0059x over previous
#include <cuda_runtime.h>
#include <cuda_fp16.h>
#include <cstdint>

// ---------------- problem constants ----------------
#define M_TOTAL 8192
#define K_DIM   4096
#define N_DIM   4096
#define LRANK   16

#define TM 128
#define TN 128
#define KC 64                     // fp16 elems per k-chunk (128B rows, SW128)
#define NCHUNK (K_DIM / KC)       // 64
#define MT (M_TOTAL / TM)         // 64
#define NT (N_DIM / TN)           // 32

#define A_BLK 16384               // 128x64 fp16
#define W_BLK 16384               // 128x64 fp16
#define STAGE_BYTES 32768         // A_BLK + W_BLK
#define NSTAGE 3
#define SMEM_TOTAL (NSTAGE * STAGE_BYTES)   // 98304 -> 2 CTAs/SM

// pre-converted, pre-swizzled operands (device globals = sanctioned scratch)
__device__ __align__(1024) unsigned char g_x[(size_t)MT * NCHUNK * A_BLK]; // 64MB
__device__ __align__(1024) unsigned char g_w[(size_t)NT * NCHUNK * W_BLK]; // 32MB

static __device__ __forceinline__ uint32_t smem_u32(const void* p) {
    uint32_t a;
    asm("{ .reg .u64 t; cvta.to.shared.u64 t, %1; cvt.u32.u64 %0, t; }" : "=r"(a) : "l"(p));
    return a;
}

static __device__ __forceinline__ void cp16(uint32_t dst, const void* src) {
    asm volatile("cp.async.cg.shared.global [%0], [%1], 16;" :: "r"(dst), "l"(src) : "memory");
}

#define LDSM_X4(r0, r1, r2, r3, addr)                                          \
    asm volatile("ldmatrix.sync.aligned.m8n8.x4.shared.b16 {%0,%1,%2,%3}, [%4];" \
        : "=r"(r0), "=r"(r1), "=r"(r2), "=r"(r3) : "r"(addr))

#define MMA16816(d, a0, a1, a2, a3, b0, b1)                                    \
    asm volatile("mma.sync.aligned.m16n8k16.row.col.f32.f16.f16.f32 "          \
        "{%0,%1,%2,%3}, {%4,%5,%6,%7}, {%8,%9}, {%0,%1,%2,%3};"                \
        : "+f"((d)[0]), "+f"((d)[1]), "+f"((d)[2]), "+f"((d)[3])               \
        : "r"(a0), "r"(a1), "r"(a2), "r"(a3), "r"(b0), "r"(b1))

// pack 8 floats -> 8 halves (uint4)
static __device__ __forceinline__ uint4 pack8(const float* v) {
    union { uint4 u; __half2 h[4]; } o;
    o.h[0] = __float22half2_rn(make_float2(v[0], v[1]));
    o.h[1] = __float22half2_rn(make_float2(v[2], v[3]));
    o.h[2] = __float22half2_rn(make_float2(v[4], v[5]));
    o.h[3] = __float22half2_rn(make_float2(v[6], v[7]));
    return o.u;
}

// ---------------------------------------------------------------------------
// conv_x body: x fp32 -> fp16, SW128-swizzled 128x64 blocks
// 8 contiguous k-elems per thread -> one 16B store (swizzle is 16B-granular)
// ---------------------------------------------------------------------------
static __device__ __forceinline__ void conv_x_body(const float* __restrict__ x,
                                                   int kc, int mt, int t)
{
    const int k0 = kc * KC, m0 = mt * TM;
    unsigned char* blk = g_x + ((size_t)(mt * NCHUNK + kc) * A_BLK);
    #pragma unroll
    for (int i = 0; i < 4; i++) {                 // 1024 items of 8 elems
        int e = t + 256 * i;
        int r = e >> 3, c8 = (e & 7) * 8;
        const float* src = &x[(size_t)(m0 + r) * K_DIM + k0 + c8];
        float v[8];
        *(float4*)&v[0] = *(const float4*)(src);
        *(float4*)&v[4] = *(const float4*)(src + 4);
        uint32_t off = (uint32_t)r * 128 + (uint32_t)c8 * 2;
        uint32_t sw = off ^ ((off >> 3) & 0x70);
        *(uint4*)(blk + sw) = pack8(v);
    }
}

// ---------------------------------------------------------------------------
// conv_w body: W' = W + B@A -> fp16, SW128-swizzled 128x64 blocks
// each call does 64 n-rows x 64 k-cols (by in [0,64))
// ---------------------------------------------------------------------------
static __device__ __forceinline__ void conv_w_body(const float* __restrict__ W,
                                                   const float* __restrict__ Amat,
                                                   const float* __restrict__ Bmat,
                                                   int kc, int by, int t,
                                                   float (*As)[64], float (*Bs)[16])
{
    const int k0 = kc * KC, n0 = by * 64;

    {   // A slab 16x64
        int r = t / 16, c4 = (t % 16) * 4;
        float4 v = *(const float4*)&Amat[(size_t)r * K_DIM + k0 + c4];
        As[r][c4+0] = v.x; As[r][c4+1] = v.y; As[r][c4+2] = v.z; As[r][c4+3] = v.w;
    }
    {   // B slab 64x16
        int nl = t / 4, r4 = (t % 4) * 4;
        float4 v = *(const float4*)&Bmat[(size_t)(n0 + nl) * LRANK + r4];
        Bs[nl][r4+0] = v.x; Bs[nl][r4+1] = v.y; Bs[nl][r4+2] = v.z; Bs[nl][r4+3] = v.w;
    }
    __syncthreads();

    const int n_tile = by >> 1;            // 128-row tiles
    const int row_base = (by & 1) * 64;
    unsigned char* blk = g_w + ((size_t)(n_tile * NCHUNK + kc) * W_BLK);

    #pragma unroll
    for (int i = 0; i < 2; i++) {                 // 512 items of 8 elems
        int e = t + 256 * i;
        int rl = e >> 3, c8 = (e & 7) * 8;
        const float* src = &W[(size_t)((size_t)n0 + rl) * K_DIM + k0 + c8];
        float v[8];
        *(float4*)&v[0] = *(const float4*)(src);
        *(float4*)&v[4] = *(const float4*)(src + 4);
        #pragma unroll
        for (int r = 0; r < 16; r++) {
            float b = Bs[rl][r];
            #pragma unroll
            for (int j = 0; j < 8; j++) v[j] += b * As[r][c8 + j];
        }
        uint32_t off = (uint32_t)(row_base + rl) * 128 + (uint32_t)c8 * 2;
        uint32_t sw = off ^ ((off >> 3) & 0x70);
        *(uint4*)(blk + sw) = pack8(v);
    }
}

// ===========================================================================
// merged conversion kernel: one wave covers both x and W' conversion
// grid (NCHUNK, 64, 2): z=0 -> conv_x (y = mt), z=1 -> conv_w (y = by)
// ===========================================================================
__global__ __launch_bounds__(256)
void conv_all_kernel(const float* __restrict__ x, const float* __restrict__ W,
                     const float* __restrict__ Amat, const float* __restrict__ Bmat)
{
    __shared__ float As[16][64];
    __shared__ float Bs[64][16];
    const int kc = blockIdx.x;
    const int y  = blockIdx.y;
    const int t  = threadIdx.x;
    if (blockIdx.z == 0) {
        conv_x_body(x, kc, y, t);
    } else {
        conv_w_body(W, Amat, Bmat, kc, y, t, As, Bs);
    }
}

// ===========================================================================
// GEMM: out = x @ W'^T + bias  via fp16 HMMA (mma.sync)
// CTA 128x128, 8 warps (4x2), warp tile 32x64, 3-stage, 1 barrier/chunk,
// 2 CTAs/SM for cross-CTA prologue/epilogue overlap
// ===========================================================================
__global__ __launch_bounds__(256, 2)
void gemm_mma_kernel(const float* __restrict__ bias, float* __restrict__ out)
{
    extern __shared__ __align__(1024) unsigned char smem[];
    const uint32_t sbase = smem_u32(smem);
    const int tid  = threadIdx.x;
    const int lane = tid & 31;
    const int wid  = tid >> 5;
    const int wm   = wid & 3;          // 4 m-groups of 32
    const int wn   = wid >> 2;         // 2 n-groups of 64
    const int nt = blockIdx.x, mt = blockIdx.y;
    const int m0 = mt * TM, n0 = nt * TN;

    const unsigned char* ga = g_x + (size_t)(mt * NCHUNK) * A_BLK;
    const unsigned char* gb = g_w + (size_t)(nt * NCHUNK) * W_BLK;

    // ---- per-thread ldmatrix addressing (SW128) ----
    const int aRow = wm * 32 + ((lane >> 3) & 1) * 8 + (lane & 7);
    const uint32_t aKsel = (lane >> 4) * 16;            // +16B for k+8 halves
    const int bRow = wn * 64 + ((lane >> 4) & 1) * 8 + (lane & 7);
    const uint32_t bKsel = ((lane >> 3) & 1) * 16;
    const uint32_t X = (uint32_t)(lane & 7) << 4;       // swizzle XOR (row&7)<<4

    float acc[2][8][4];
    #pragma unroll
    for (int i = 0; i < 2; i++)
        #pragma unroll
        for (int j = 0; j < 8; j++)
            #pragma unroll
            for (int q = 0; q < 4; q++) acc[i][j][q] = 0.f;

    // ---- async copy of one chunk into stage s (256 threads) ----
    auto issue = [&](int c, int s) {
        const unsigned char* srcA = ga + (size_t)c * A_BLK;
        const unsigned char* srcB = gb + (size_t)c * W_BLK;
        uint32_t st = sbase + s * STAGE_BYTES;
        #pragma unroll
        for (int i = 0; i < 4; i++) {                      // A: 16KB
            uint32_t off = (uint32_t)tid * 16 + i * 4096;
            cp16(st + off, srcA + off);
        }
        #pragma unroll
        for (int i = 0; i < 4; i++) {                      // B: 16KB
            uint32_t off = (uint32_t)tid * 16 + i * 4096;
            cp16(st + A_BLK + off, srcB + off);
        }
        asm volatile("cp.async.commit_group;" ::: "memory");
    };

    issue(0, 0);
    issue(1, 1);

    int s = 0, spre = 2;
    for (int c = 0; c < NCHUNK; c++) {
        asm volatile("cp.async.wait_group 1;" ::: "memory");
        __syncthreads();
        // stage spre = (c+2)%3 == (c-1)%3 was fully consumed before this barrier
        if (c + 2 < NCHUNK) issue(c + 2, spre);

        const uint32_t Ahi = sbase + s * STAGE_BYTES;
        const uint32_t Bhi = Ahi + A_BLK;

        #pragma unroll
        for (int ks = 0; ks < 4; ks++) {
            const uint32_t kb = (uint32_t)ks * 32;           // k0*2 bytes
            const uint32_t aoff = (kb + aKsel) ^ X;
            const uint32_t boff = (kb + bKsel) ^ X;

            uint32_t aH[2][4];
            #pragma unroll
            for (int m2 = 0; m2 < 2; m2++) {
                uint32_t rb = (uint32_t)(aRow + 16 * m2) * 128;
                LDSM_X4(aH[m2][0], aH[m2][1], aH[m2][2], aH[m2][3], Ahi + rb + aoff);
            }
            uint32_t bH[4][4];
            #pragma unroll
            for (int n4 = 0; n4 < 4; n4++) {
                uint32_t rb = (uint32_t)(bRow + 16 * n4) * 128;
                LDSM_X4(bH[n4][0], bH[n4][1], bH[n4][2], bH[n4][3], Bhi + rb + boff);
            }

            #pragma unroll
            for (int m2 = 0; m2 < 2; m2++) {
                #pragma unroll
                for (int nj = 0; nj < 8; nj++) {
                    const int g = nj >> 1, h = (nj & 1) * 2;
                    MMA16816(acc[m2][nj], aH[m2][0], aH[m2][1], aH[m2][2], aH[m2][3],
                             bH[g][h], bH[g][h + 1]);
                }
            }
        }

        s = (s == NSTAGE - 1) ? 0 : s + 1;
        spre = (spre == NSTAGE - 1) ? 0 : spre + 1;
    }

    // ---- epilogue: bias + store ----
    const int rrow = m0 + wm * 32 + (lane >> 2);
    const int ncol = n0 + wn * 64 + (lane & 3) * 2;

    float2 bb[8];
    #pragma unroll
    for (int nj = 0; nj < 8; nj++)
        bb[nj] = *(const float2*)&bias[ncol + nj * 8];

    #pragma unroll
    for (int m2 = 0; m2 < 2; m2++) {
        #pragma unroll
        for (int nj = 0; nj < 8; nj++) {
            const int n = ncol + nj * 8;
            size_t r0 = (size_t)(rrow + m2 * 16) * N_DIM + n;
            size_t r1 = r0 + 8 * N_DIM;
            float2 o0, o1;
            o0.x = acc[m2][nj][0] + bb[nj].x;
            o0.y = acc[m2][nj][1] + bb[nj].y;
            o1.x = acc[m2][nj][2] + bb[nj].x;
            o1.y = acc[m2][nj][3] + bb[nj].y;
            *(float2*)&out[r0] = o0;
            *(float2*)&out[r1] = o1;
        }
    }
}

// ===========================================================================
extern "C" void kernel_launch(void* const* d_in, const int* in_sizes, int n_in,
                              void* d_out, int out_size)
{
    (void)in_sizes; (void)n_in; (void)out_size;
    const float* x    = (const float*)d_in[0];
    const float* W    = (const float*)d_in[1];
    const float* bias = (const float*)d_in[2];
    const float* A    = (const float*)d_in[3];
    const float* Bm   = (const float*)d_in[4];
    float* out        = (float*)d_out;

    cudaFuncSetAttribute(gemm_mma_kernel,
                         cudaFuncAttributeMaxDynamicSharedMemorySize, SMEM_TOTAL);

    conv_all_kernel<<<dim3(NCHUNK, 64, 2), 256>>>(x, W, A, Bm);
    gemm_mma_kernel<<<dim3(NT, MT), 256, SMEM_TOTAL>>>(bias, out);
}

// round 13
// speedup vs baseline: 1.0769x; 1.0276x over previous
#include <cuda_runtime.h>
#include <cuda_fp16.h>
#include <cstdint>

// ---------------- problem constants ----------------
#define M_TOTAL 8192
#define K_DIM   4096
#define N_DIM   4096
#define LRANK   16

#define TM 128
#define TN 128
#define KC 64                     // fp16 elems per k-chunk (128B rows, SW128)
#define NCHUNK (K_DIM / KC)       // 64
#define MT (M_TOTAL / TM)         // 64
#define NT (N_DIM / TN)           // 32

#define A_BLK 16384               // 128x64 fp16
#define W_BLK 16384               // 128x64 fp16
#define STAGE_BYTES 32768         // A_BLK + W_BLK
#define NSTAGE 3
#define SMEM_TOTAL (NSTAGE * STAGE_BYTES)   // 98304 -> 2 CTAs/SM

// pre-converted, pre-swizzled operands (device globals = sanctioned scratch)
__device__ __align__(1024) unsigned char g_x[(size_t)MT * NCHUNK * A_BLK]; // 64MB
__device__ __align__(1024) unsigned char g_w[(size_t)NT * NCHUNK * W_BLK]; // 32MB

static __device__ __forceinline__ uint32_t smem_u32(const void* p) {
    uint32_t a;
    asm("{ .reg .u64 t; cvta.to.shared.u64 t, %1; cvt.u32.u64 %0, t; }" : "=r"(a) : "l"(p));
    return a;
}

static __device__ __forceinline__ void cp16(uint32_t dst, const void* src) {
    asm volatile("cp.async.cg.shared.global [%0], [%1], 16;" :: "r"(dst), "l"(src) : "memory");
}

#define LDSM_X4(r0, r1, r2, r3, addr)                                          \
    asm volatile("ldmatrix.sync.aligned.m8n8.x4.shared.b16 {%0,%1,%2,%3}, [%4];" \
        : "=r"(r0), "=r"(r1), "=r"(r2), "=r"(r3) : "r"(addr))

#define MMA16816(d, a0, a1, a2, a3, b0, b1)                                    \
    asm volatile("mma.sync.aligned.m16n8k16.row.col.f32.f16.f16.f32 "          \
        "{%0,%1,%2,%3}, {%4,%5,%6,%7}, {%8,%9}, {%0,%1,%2,%3};"                \
        : "+f"((d)[0]), "+f"((d)[1]), "+f"((d)[2]), "+f"((d)[3])               \
        : "r"(a0), "r"(a1), "r"(a2), "r"(a3), "r"(b0), "r"(b1))

// pack 8 floats -> 8 halves (uint4)
static __device__ __forceinline__ uint4 pack8(const float* v) {
    union { uint4 u; __half2 h[4]; } o;
    o.h[0] = __float22half2_rn(make_float2(v[0], v[1]));
    o.h[1] = __float22half2_rn(make_float2(v[2], v[3]));
    o.h[2] = __float22half2_rn(make_float2(v[4], v[5]));
    o.h[3] = __float22half2_rn(make_float2(v[6], v[7]));
    return o.u;
}

// ---------------------------------------------------------------------------
// conv_x body: x fp32 -> fp16, SW128-swizzled 128x64 blocks
// ---------------------------------------------------------------------------
static __device__ __forceinline__ void conv_x_body(const float* __restrict__ x,
                                                   int kc, int mt, int t)
{
    const int k0 = kc * KC, m0 = mt * TM;
    unsigned char* blk = g_x + ((size_t)(mt * NCHUNK + kc) * A_BLK);
    #pragma unroll
    for (int i = 0; i < 4; i++) {                 // 1024 items of 8 elems
        int e = t + 256 * i;
        int r = e >> 3, c8 = (e & 7) * 8;
        const float* src = &x[(size_t)(m0 + r) * K_DIM + k0 + c8];
        float v[8];
        *(float4*)&v[0] = *(const float4*)(src);
        *(float4*)&v[4] = *(const float4*)(src + 4);
        uint32_t off = (uint32_t)r * 128 + (uint32_t)c8 * 2;
        uint32_t sw = off ^ ((off >> 3) & 0x70);
        *(uint4*)(blk + sw) = pack8(v);
    }
}

// ---------------------------------------------------------------------------
// conv_w body: W' = W + B@A -> fp16, SW128-swizzled 128x64 blocks
// ---------------------------------------------------------------------------
static __device__ __forceinline__ void conv_w_body(const float* __restrict__ W,
                                                   const float* __restrict__ Amat,
                                                   const float* __restrict__ Bmat,
                                                   int kc, int by, int t,
                                                   float (*As)[64], float (*Bs)[16])
{
    const int k0 = kc * KC, n0 = by * 64;

    {   // A slab 16x64
        int r = t / 16, c4 = (t % 16) * 4;
        float4 v = *(const float4*)&Amat[(size_t)r * K_DIM + k0 + c4];
        As[r][c4+0] = v.x; As[r][c4+1] = v.y; As[r][c4+2] = v.z; As[r][c4+3] = v.w;
    }
    {   // B slab 64x16
        int nl = t / 4, r4 = (t % 4) * 4;
        float4 v = *(const float4*)&Bmat[(size_t)(n0 + nl) * LRANK + r4];
        Bs[nl][r4+0] = v.x; Bs[nl][r4+1] = v.y; Bs[nl][r4+2] = v.z; Bs[nl][r4+3] = v.w;
    }
    __syncthreads();

    const int n_tile = by >> 1;            // 128-row tiles
    const int row_base = (by & 1) * 64;
    unsigned char* blk = g_w + ((size_t)(n_tile * NCHUNK + kc) * W_BLK);

    #pragma unroll
    for (int i = 0; i < 2; i++) {                 // 512 items of 8 elems
        int e = t + 256 * i;
        int rl = e >> 3, c8 = (e & 7) * 8;
        const float* src = &W[(size_t)((size_t)n0 + rl) * K_DIM + k0 + c8];
        float v[8];
        *(float4*)&v[0] = *(const float4*)(src);
        *(float4*)&v[4] = *(const float4*)(src + 4);
        #pragma unroll
        for (int r = 0; r < 16; r++) {
            float b = Bs[rl][r];
            #pragma unroll
            for (int j = 0; j < 8; j++) v[j] += b * As[r][c8 + j];
        }
        uint32_t off = (uint32_t)(row_base + rl) * 128 + (uint32_t)c8 * 2;
        uint32_t sw = off ^ ((off >> 3) & 0x70);
        *(uint4*)(blk + sw) = pack8(v);
    }
}

// ===========================================================================
// merged conversion kernel
// grid (NCHUNK, 64, 2): z=0 -> conv_x (y = mt), z=1 -> conv_w (y = by)
// ===========================================================================
__global__ __launch_bounds__(256)
void conv_all_kernel(const float* __restrict__ x, const float* __restrict__ W,
                     const float* __restrict__ Amat, const float* __restrict__ Bmat)
{
    __shared__ float As[16][64];
    __shared__ float Bs[64][16];
    const int kc = blockIdx.x;
    const int y  = blockIdx.y;
    const int t  = threadIdx.x;
    if (blockIdx.z == 0) {
        conv_x_body(x, kc, y, t);
    } else {
        conv_w_body(W, Amat, Bmat, kc, y, t, As, Bs);
    }
}

// ===========================================================================
// GEMM: out = x @ W'^T + bias  via fp16 HMMA (mma.sync)
// CTA 128x128, 4 warps (2x2), warp tile 64x64, 3-stage, 1 barrier/chunk,
// 2 CTAs/SM.  64x64 warp tile cuts LDSM crossbar traffic 33% vs 32x64.
// ===========================================================================
__global__ __launch_bounds__(128, 2)
void gemm_mma_kernel(const float* __restrict__ bias, float* __restrict__ out)
{
    extern __shared__ __align__(1024) unsigned char smem[];
    const uint32_t sbase = smem_u32(smem);
    const int tid  = threadIdx.x;
    const int lane = tid & 31;
    const int wid  = tid >> 5;
    const int wm   = wid & 1;          // 2 m-groups of 64
    const int wn   = wid >> 1;         // 2 n-groups of 64
    const int nt = blockIdx.x, mt = blockIdx.y;
    const int m0 = mt * TM, n0 = nt * TN;

    const unsigned char* ga = g_x + (size_t)(mt * NCHUNK) * A_BLK;
    const unsigned char* gb = g_w + (size_t)(nt * NCHUNK) * W_BLK;

    // ---- per-thread ldmatrix addressing (SW128) ----
    const int aRow = wm * 64 + ((lane >> 3) & 1) * 8 + (lane & 7);
    const uint32_t aKsel = (lane >> 4) * 16;            // +16B for k+8 halves
    const int bRow = wn * 64 + ((lane >> 4) & 1) * 8 + (lane & 7);
    const uint32_t bKsel = ((lane >> 3) & 1) * 16;
    const uint32_t X = (uint32_t)(lane & 7) << 4;       // swizzle XOR (row&7)<<4

    float acc[4][8][4];
    #pragma unroll
    for (int i = 0; i < 4; i++)
        #pragma unroll
        for (int j = 0; j < 8; j++)
            #pragma unroll
            for (int q = 0; q < 4; q++) acc[i][j][q] = 0.f;

    // ---- async copy of one chunk into stage s (128 threads) ----
    auto issue = [&](int c, int s) {
        const unsigned char* srcA = ga + (size_t)c * A_BLK;
        const unsigned char* srcB = gb + (size_t)c * W_BLK;
        uint32_t st = sbase + s * STAGE_BYTES;
        #pragma unroll
        for (int i = 0; i < 8; i++) {                      // A: 16KB
            uint32_t off = (uint32_t)tid * 16 + i * 2048;
            cp16(st + off, srcA + off);
        }
        #pragma unroll
        for (int i = 0; i < 8; i++) {                      // B: 16KB
            uint32_t off = (uint32_t)tid * 16 + i * 2048;
            cp16(st + A_BLK + off, srcB + off);
        }
        asm volatile("cp.async.commit_group;" ::: "memory");
    };

    issue(0, 0);
    issue(1, 1);

    int s = 0, spre = 2;
    for (int c = 0; c < NCHUNK; c++) {
        asm volatile("cp.async.wait_group 1;" ::: "memory");
        __syncthreads();
        // stage spre = (c+2)%3 == (c-1)%3 was fully consumed before this barrier
        if (c + 2 < NCHUNK) issue(c + 2, spre);

        const uint32_t Ahi = sbase + s * STAGE_BYTES;
        const uint32_t Bhi = Ahi + A_BLK;

        #pragma unroll
        for (int ks = 0; ks < 4; ks++) {
            const uint32_t kb = (uint32_t)ks * 32;           // k0*2 bytes
            const uint32_t aoff = (kb + aKsel) ^ X;
            const uint32_t boff = (kb + bKsel) ^ X;

            uint32_t aH[4][4];
            #pragma unroll
            for (int m4 = 0; m4 < 4; m4++) {
                uint32_t rb = (uint32_t)(aRow + 16 * m4) * 128;
                LDSM_X4(aH[m4][0], aH[m4][1], aH[m4][2], aH[m4][3], Ahi + rb + aoff);
            }
            uint32_t bH[4][4];
            #pragma unroll
            for (int n4 = 0; n4 < 4; n4++) {
                uint32_t rb = (uint32_t)(bRow + 16 * n4) * 128;
                LDSM_X4(bH[n4][0], bH[n4][1], bH[n4][2], bH[n4][3], Bhi + rb + boff);
            }

            #pragma unroll
            for (int m4 = 0; m4 < 4; m4++) {
                #pragma unroll
                for (int nj = 0; nj < 8; nj++) {
                    const int g = nj >> 1, h = (nj & 1) * 2;
                    MMA16816(acc[m4][nj], aH[m4][0], aH[m4][1], aH[m4][2], aH[m4][3],
                             bH[g][h], bH[g][h + 1]);
                }
            }
        }

        s = (s == NSTAGE - 1) ? 0 : s + 1;
        spre = (spre == NSTAGE - 1) ? 0 : spre + 1;
    }

    // ---- epilogue: bias + store ----
    const int rrow = m0 + wm * 64 + (lane >> 2);
    const int ncol = n0 + wn * 64 + (lane & 3) * 2;

    float2 bb[8];
    #pragma unroll
    for (int nj = 0; nj < 8; nj++)
        bb[nj] = *(const float2*)&bias[ncol + nj * 8];

    #pragma unroll
    for (int m4 = 0; m4 < 4; m4++) {
        #pragma unroll
        for (int nj = 0; nj < 8; nj++) {
            const int n = ncol + nj * 8;
            size_t r0 = (size_t)(rrow + m4 * 16) * N_DIM + n;
            size_t r1 = r0 + 8 * N_DIM;
            float2 o0, o1;
            o0.x = acc[m4][nj][0] + bb[nj].x;
            o0.y = acc[m4][nj][1] + bb[nj].y;
            o1.x = acc[m4][nj][2] + bb[nj].x;
            o1.y = acc[m4][nj][3] + bb[nj].y;
            *(float2*)&out[r0] = o0;
            *(float2*)&out[r1] = o1;
        }
    }
}

// ===========================================================================
extern "C" void kernel_launch(void* const* d_in, const int* in_sizes, int n_in,
                              void* d_out, int out_size)
{
    (void)in_sizes; (void)n_in; (void)out_size;
    const float* x    = (const float*)d_in[0];
    const float* W    = (const float*)d_in[1];
    const float* bias = (const float*)d_in[2];
    const float* A    = (const float*)d_in[3];
    const float* Bm   = (const float*)d_in[4];
    float* out        = (float*)d_out;

    cudaFuncSetAttribute(gemm_mma_kernel,
                         cudaFuncAttributeMaxDynamicSharedMemorySize, SMEM_TOTAL);

    conv_all_kernel<<<dim3(NCHUNK, 64, 2), 256>>>(x, W, A, Bm);
    gemm_mma_kernel<<<dim3(NT, MT), 128, SMEM_TOTAL>>>(bias, out);
}

// round 14
// speedup vs baseline: 1.2211x; 1.1339x over previous
#include <cuda_runtime.h>
#include <cuda_fp16.h>
#include <cstdint>

// ---------------- problem constants ----------------
#define M_TOTAL 8192
#define K_DIM   4096
#define N_DIM   4096
#define LRANK   16

#define TM 128
#define TN 128
#define KC 64                     // fp16 elems per k-chunk (128B rows, SW128)
#define NCHUNK (K_DIM / KC)       // 64
#define MT (M_TOTAL / TM)         // 64
#define NT (N_DIM / TN)           // 32

#define A_BLK 16384               // 128x64 fp16
#define W_BLK 16384               // 128x64 fp16
#define STAGE_BYTES 32768         // A_BLK + W_BLK
#define NSTAGE 3
#define BARS_OFF (NSTAGE * STAGE_BYTES)     // 98304
#define SMEM_TOTAL (BARS_OFF + 64)          // 98368 -> 2 CTAs/SM

// pre-converted, pre-swizzled operands (device globals = sanctioned scratch)
__device__ __align__(1024) unsigned char g_x[(size_t)MT * NCHUNK * A_BLK]; // 64MB
__device__ __align__(1024) unsigned char g_w[(size_t)NT * NCHUNK * W_BLK]; // 32MB

static __device__ __forceinline__ uint32_t smem_u32(const void* p) {
    uint32_t a;
    asm("{ .reg .u64 t; cvta.to.shared.u64 t, %1; cvt.u32.u64 %0, t; }" : "=r"(a) : "l"(p));
    return a;
}

#define MBAR_INIT(addr, cnt) \
    asm volatile("mbarrier.init.shared.b64 [%0], %1;" :: "r"(addr), "r"(cnt) : "memory")
#define MBAR_EXPECT_TX(addr, bytes) \
    asm volatile("mbarrier.arrive.expect_tx.shared.b64 _, [%0], %1;" :: "r"(addr), "r"(bytes) : "memory")
#define MBAR_ARRIVE(addr) \
    asm volatile("mbarrier.arrive.shared.b64 _, [%0];" :: "r"(addr) : "memory")

#define MBAR_WAIT(addr, parity) do {                                          \
    uint32_t _m = (addr), _p = (parity), _d;                                  \
    asm volatile("{\n\t.reg .pred p;\n\t"                                     \
        "mbarrier.try_wait.parity.acquire.cta.shared::cta.b64 p, [%1], %2;\n\t" \
        "selp.b32 %0, 1, 0, p;\n\t}"                                          \
        : "=r"(_d) : "r"(_m), "r"(_p) : "memory");                            \
    if (!_d) {                                                                \
        asm volatile("{\n\t.reg .pred P1;\n\t"                                \
        "WL_%=:\n\t"                                                          \
        "mbarrier.try_wait.parity.acquire.cta.shared::cta.b64 P1, [%0], %1, 0x989680;\n\t" \
        "@P1 bra.uni WD_%=;\n\t"                                              \
        "bra.uni WL_%=;\n\t"                                                  \
        "WD_%=:\n\t}" :: "r"(_m), "r"(_p) : "memory");                        \
    }                                                                         \
} while (0)

static __device__ __forceinline__ void bulk_g2s(uint32_t dst, const void* src,
                                                uint32_t bytes, uint32_t mbar) {
    asm volatile(
        "cp.async.bulk.shared::cta.global.mbarrier::complete_tx::bytes [%0], [%1], %2, [%3];"
        :: "r"(dst), "l"(src), "r"(bytes), "r"(mbar) : "memory");
}

#define LDSM_X4(r0, r1, r2, r3, addr)                                          \
    asm volatile("ldmatrix.sync.aligned.m8n8.x4.shared.b16 {%0,%1,%2,%3}, [%4];" \
        : "=r"(r0), "=r"(r1), "=r"(r2), "=r"(r3) : "r"(addr))

#define MMA16816(d, a0, a1, a2, a3, b0, b1)                                    \
    asm volatile("mma.sync.aligned.m16n8k16.row.col.f32.f16.f16.f32 "          \
        "{%0,%1,%2,%3}, {%4,%5,%6,%7}, {%8,%9}, {%0,%1,%2,%3};"                \
        : "+f"((d)[0]), "+f"((d)[1]), "+f"((d)[2]), "+f"((d)[3])               \
        : "r"(a0), "r"(a1), "r"(a2), "r"(a3), "r"(b0), "r"(b1))

// pack 8 floats -> 8 halves (uint4)
static __device__ __forceinline__ uint4 pack8(const float* v) {
    union { uint4 u; __half2 h[4]; } o;
    o.h[0] = __float22half2_rn(make_float2(v[0], v[1]));
    o.h[1] = __float22half2_rn(make_float2(v[2], v[3]));
    o.h[2] = __float22half2_rn(make_float2(v[4], v[5]));
    o.h[3] = __float22half2_rn(make_float2(v[6], v[7]));
    return o.u;
}

// ---------------------------------------------------------------------------
// conv_x body: x fp32 -> fp16, SW128-swizzled 128x64 blocks
// ---------------------------------------------------------------------------
static __device__ __forceinline__ void conv_x_body(const float* __restrict__ x,
                                                   int kc, int mt, int t)
{
    const int k0 = kc * KC, m0 = mt * TM;
    unsigned char* blk = g_x + ((size_t)(mt * NCHUNK + kc) * A_BLK);
    #pragma unroll
    for (int i = 0; i < 4; i++) {                 // 1024 items of 8 elems
        int e = t + 256 * i;
        int r = e >> 3, c8 = (e & 7) * 8;
        const float* src = &x[(size_t)(m0 + r) * K_DIM + k0 + c8];
        float v[8];
        *(float4*)&v[0] = *(const float4*)(src);
        *(float4*)&v[4] = *(const float4*)(src + 4);
        uint32_t off = (uint32_t)r * 128 + (uint32_t)c8 * 2;
        uint32_t sw = off ^ ((off >> 3) & 0x70);
        *(uint4*)(blk + sw) = pack8(v);
    }
}

// ---------------------------------------------------------------------------
// conv_w body: W' = W + B@A -> fp16, SW128-swizzled 128x64 blocks
// ---------------------------------------------------------------------------
static __device__ __forceinline__ void conv_w_body(const float* __restrict__ W,
                                                   const float* __restrict__ Amat,
                                                   const float* __restrict__ Bmat,
                                                   int kc, int by, int t,
                                                   float (*As)[64], float (*Bs)[16])
{
    const int k0 = kc * KC, n0 = by * 64;

    {   // A slab 16x64
        int r = t / 16, c4 = (t % 16) * 4;
        float4 v = *(const float4*)&Amat[(size_t)r * K_DIM + k0 + c4];
        As[r][c4+0] = v.x; As[r][c4+1] = v.y; As[r][c4+2] = v.z; As[r][c4+3] = v.w;
    }
    {   // B slab 64x16
        int nl = t / 4, r4 = (t % 4) * 4;
        float4 v = *(const float4*)&Bmat[(size_t)(n0 + nl) * LRANK + r4];
        Bs[nl][r4+0] = v.x; Bs[nl][r4+1] = v.y; Bs[nl][r4+2] = v.z; Bs[nl][r4+3] = v.w;
    }
    __syncthreads();

    const int n_tile = by >> 1;            // 128-row tiles
    const int row_base = (by & 1) * 64;
    unsigned char* blk = g_w + ((size_t)(n_tile * NCHUNK + kc) * W_BLK);

    #pragma unroll
    for (int i = 0; i < 2; i++) {                 // 512 items of 8 elems
        int e = t + 256 * i;
        int rl = e >> 3, c8 = (e & 7) * 8;
        const float* src = &W[(size_t)((size_t)n0 + rl) * K_DIM + k0 + c8];
        float v[8];
        *(float4*)&v[0] = *(const float4*)(src);
        *(float4*)&v[4] = *(const float4*)(src + 4);
        #pragma unroll
        for (int r = 0; r < 16; r++) {
            float b = Bs[rl][r];
            #pragma unroll
            for (int j = 0; j < 8; j++) v[j] += b * As[r][c8 + j];
        }
        uint32_t off = (uint32_t)(row_base + rl) * 128 + (uint32_t)c8 * 2;
        uint32_t sw = off ^ ((off >> 3) & 0x70);
        *(uint4*)(blk + sw) = pack8(v);
    }
}

// ===========================================================================
// merged conversion kernel
// grid (NCHUNK, 64, 2): z=0 -> conv_x (y = mt), z=1 -> conv_w (y = by)
// ===========================================================================
__global__ __launch_bounds__(256)
void conv_all_kernel(const float* __restrict__ x, const float* __restrict__ W,
                     const float* __restrict__ Amat, const float* __restrict__ Bmat)
{
    __shared__ float As[16][64];
    __shared__ float Bs[64][16];
    const int kc = blockIdx.x;
    const int y  = blockIdx.y;
    const int t  = threadIdx.x;
    if (blockIdx.z == 0) {
        conv_x_body(x, kc, y, t);
    } else {
        conv_w_body(W, Amat, Bmat, kc, y, t, As, Bs);
    }
}

// ===========================================================================
// GEMM: out = x @ W'^T + bias  via fp16 HMMA (mma.sync)
// CTA 128x128, 4 warps (2x2), warp tile 64x64, 3-stage mbarrier pipeline.
// No per-chunk __syncthreads: cp.async.bulk (thread 0) + full/empty mbarriers;
// warps drift freely so LDSM bursts interleave with other warps' MMA drain.
// ===========================================================================
__global__ __launch_bounds__(128, 2)
void gemm_mma_kernel(const float* __restrict__ bias, float* __restrict__ out)
{
    extern __shared__ __align__(1024) unsigned char smem[];
    const uint32_t sbase = smem_u32(smem);
    const int tid  = threadIdx.x;
    const int lane = tid & 31;
    const int wid  = tid >> 5;
    const int wm   = wid & 1;          // 2 m-groups of 64
    const int wn   = wid >> 1;         // 2 n-groups of 64
    const int nt = blockIdx.x, mt = blockIdx.y;
    const int m0 = mt * TM, n0 = nt * TN;

    const unsigned char* ga = g_x + (size_t)(mt * NCHUNK) * A_BLK;
    const unsigned char* gb = g_w + (size_t)(nt * NCHUNK) * W_BLK;

    const uint32_t barF = sbase + BARS_OFF;        // 3 x 8B full barriers
    const uint32_t barE = sbase + BARS_OFF + 24;   // 3 x 8B empty barriers

    // ---- init barriers, prime 3 stages ----
    if (tid == 0) {
        #pragma unroll
        for (int s = 0; s < NSTAGE; s++) {
            MBAR_INIT(barF + s * 8, 1);
            MBAR_INIT(barE + s * 8, 4);
        }
    }
    __syncthreads();
    if (tid == 0) {
        #pragma unroll
        for (int s = 0; s < NSTAGE; s++) {
            uint32_t st = sbase + s * STAGE_BYTES;
            MBAR_EXPECT_TX(barF + s * 8, STAGE_BYTES);
            bulk_g2s(st,         ga + (size_t)s * A_BLK, A_BLK, barF + s * 8);
            bulk_g2s(st + A_BLK, gb + (size_t)s * W_BLK, W_BLK, barF + s * 8);
        }
    }

    // ---- per-thread ldmatrix addressing (SW128) ----
    const int aRow = wm * 64 + ((lane >> 3) & 1) * 8 + (lane & 7);
    const uint32_t aKsel = (lane >> 4) * 16;            // +16B for k+8 halves
    const int bRow = wn * 64 + ((lane >> 4) & 1) * 8 + (lane & 7);
    const uint32_t bKsel = ((lane >> 3) & 1) * 16;
    const uint32_t X = (uint32_t)(lane & 7) << 4;       // swizzle XOR (row&7)<<4

    float acc[4][8][4];
    #pragma unroll
    for (int i = 0; i < 4; i++)
        #pragma unroll
        for (int j = 0; j < 8; j++)
            #pragma unroll
            for (int q = 0; q < 4; q++) acc[i][j][q] = 0.f;

    int pF0 = 0, pF1 = 0, pF2 = 0;     // full parities per stage
    int pE0 = 0, pE1 = 0, pE2 = 0;     // empty parities per stage

    int s = 0;
    for (int c = 0; c < NCHUNK; c++) {
        const uint32_t bF = barF + s * 8;
        const uint32_t bE = barE + s * 8;
        int pF = (s == 0) ? pF0 : (s == 1) ? pF1 : pF2;

        MBAR_WAIT(bF, pF);
        if (s == 0) pF0 ^= 1; else if (s == 1) pF1 ^= 1; else pF2 ^= 1;

        const uint32_t Ahi = sbase + s * STAGE_BYTES;
        const uint32_t Bhi = Ahi + A_BLK;

        #pragma unroll
        for (int ks = 0; ks < 4; ks++) {
            const uint32_t kb = (uint32_t)ks * 32;           // k0*2 bytes
            const uint32_t aoff = (kb + aKsel) ^ X;
            const uint32_t boff = (kb + bKsel) ^ X;

            uint32_t aH[4][4];
            #pragma unroll
            for (int m4 = 0; m4 < 4; m4++) {
                uint32_t rb = (uint32_t)(aRow + 16 * m4) * 128;
                LDSM_X4(aH[m4][0], aH[m4][1], aH[m4][2], aH[m4][3], Ahi + rb + aoff);
            }
            uint32_t bH[4][4];
            #pragma unroll
            for (int n4 = 0; n4 < 4; n4++) {
                uint32_t rb = (uint32_t)(bRow + 16 * n4) * 128;
                LDSM_X4(bH[n4][0], bH[n4][1], bH[n4][2], bH[n4][3], Bhi + rb + boff);
            }

            #pragma unroll
            for (int m4 = 0; m4 < 4; m4++) {
                #pragma unroll
                for (int nj = 0; nj < 8; nj++) {
                    const int g = nj >> 1, h = (nj & 1) * 2;
                    MMA16816(acc[m4][nj], aH[m4][0], aH[m4][1], aH[m4][2], aH[m4][3],
                             bH[g][h], bH[g][h + 1]);
                }
            }
        }

        // release the stage: MMA issue above required all frag regs ready,
        // so every LDSM of this stage has completed before this arrive.
        if (lane == 0) MBAR_ARRIVE(bE);

        // producer: refill stage s with chunk c+3 once all 4 warps released it
        if (tid == 0 && c + 3 < NCHUNK) {
            int pE = (s == 0) ? pE0 : (s == 1) ? pE1 : pE2;
            MBAR_WAIT(bE, pE);
            if (s == 0) pE0 ^= 1; else if (s == 1) pE1 ^= 1; else pE2 ^= 1;
            uint32_t st = sbase + s * STAGE_BYTES;
            MBAR_EXPECT_TX(bF, STAGE_BYTES);
            bulk_g2s(st,         ga + (size_t)(c + 3) * A_BLK, A_BLK, bF);
            bulk_g2s(st + A_BLK, gb + (size_t)(c + 3) * W_BLK, W_BLK, bF);
        }

        s = (s == NSTAGE - 1) ? 0 : s + 1;
    }

    // ---- epilogue: bias + store ----
    const int rrow = m0 + wm * 64 + (lane >> 2);
    const int ncol = n0 + wn * 64 + (lane & 3) * 2;

    float2 bb[8];
    #pragma unroll
    for (int nj = 0; nj < 8; nj++)
        bb[nj] = *(const float2*)&bias[ncol + nj * 8];

    #pragma unroll
    for (int m4 = 0; m4 < 4; m4++) {
        #pragma unroll
        for (int nj = 0; nj < 8; nj++) {
            const int n = ncol + nj * 8;
            size_t r0 = (size_t)(rrow + m4 * 16) * N_DIM + n;
            size_t r1 = r0 + 8 * N_DIM;
            float2 o0, o1;
            o0.x = acc[m4][nj][0] + bb[nj].x;
            o0.y = acc[m4][nj][1] + bb[nj].y;
            o1.x = acc[m4][nj][2] + bb[nj].x;
            o1.y = acc[m4][nj][3] + bb[nj].y;
            *(float2*)&out[r0] = o0;
            *(float2*)&out[r1] = o1;
        }
    }
}

// ===========================================================================
extern "C" void kernel_launch(void* const* d_in, const int* in_sizes, int n_in,
                              void* d_out, int out_size)
{
    (void)in_sizes; (void)n_in; (void)out_size;
    const float* x    = (const float*)d_in[0];
    const float* W    = (const float*)d_in[1];
    const float* bias = (const float*)d_in[2];
    const float* A    = (const float*)d_in[3];
    const float* Bm   = (const float*)d_in[4];
    float* out        = (float*)d_out;

    cudaFuncSetAttribute(gemm_mma_kernel,
                         cudaFuncAttributeMaxDynamicSharedMemorySize, SMEM_TOTAL);

    conv_all_kernel<<<dim3(NCHUNK, 64, 2), 256>>>(x, W, A, Bm);
    gemm_mma_kernel<<<dim3(NT, MT), 128, SMEM_TOTAL>>>(bias, out);
}